// round 16
// baseline (speedup 1.0000x reference)
#include <cuda_runtime.h>
#include <cuda_bf16.h>
#include <cstdint>

// B=32, W=256, N=512, thresholds {0.3,0.5,0.7}
// out: (B,6) fp32 [t0_b0,t0_b1,t1_b0,t1_b1,t2_b0,t2_b1]

#define BATCH 32
#define WIN   256
#define NA    512
#define CAP   131072   // >= 512*511/2
#define KCH   64       // bf16 per K-chunk (128 B rows)
#define NCH   4        // K = 256 (h.h only; band+fixup covers the bf16 error)
#define NSTG  3
#define STAGE_BYTES 24576   // 16KB A(128 rows) + 8KB B(64 rows)
#define SMEM_DYN    (NSTG * STAGE_BYTES)
#define NTILE 20
#define BAND  4.5e-3f       // certified |corr_exact - corr_hh| bound is 3.9e-3
#define SCAPB 2048          // per-batch suspect cap (expected ~0-2)

// ---------------- device scratch ----------------
__device__ __nv_bfloat16 g_h[BATCH][NA][WIN];   // 8 MB
__device__ int   g_ecnt[3][BATCH];
__device__ unsigned int g_edges[3][BATCH][CAP];
__device__ int   g_scnt_b[BATCH];
__device__ unsigned int g_susp[BATCH][SCAPB];   // (mask<<23)|(gi<<9)|gj
__device__ int   g_done[BATCH];

__device__ __forceinline__ uint32_t smem_u32(const void* p) {
    uint32_t a;
    asm("{ .reg .u64 t; cvta.to.shared.u64 t, %1; cvt.u32.u64 %0, t; }" : "=r"(a) : "l"(p));
    return a;
}
#define SW128(x) ((x) ^ (((x) >> 3) & 0x70))
#define CP16(dst, src) \
    asm volatile("cp.async.cg.shared.global [%0], [%1], 16;" :: "r"(dst), "l"(src))
#define CPCOMMIT() asm volatile("cp.async.commit_group;" ::: "memory")
#define CPWAIT1()  asm volatile("cp.async.wait_group 1;" ::: "memory")
#define CPWAIT0()  asm volatile("cp.async.wait_group 0;" ::: "memory")

// ------- fused stats + normalize + bf16(h) + transpose (one smem pass) -------
// CTA: 32 assets x 256 w. grid (16, 32). 512 threads: a = t&31, q = t>>5.
__global__ void __launch_bounds__(512)
convert_kernel(const float* __restrict__ ret) {
    __shared__ __align__(16) float fsm[WIN][32];   // 32 KB
    __shared__ float ps[16][32], ps2[16][32], mean_s[32], inv_s[32];

    const int b = blockIdx.y, n0 = blockIdx.x * 32;
    const int t = threadIdx.x;

    // per-batch zeroing (stream-ordered before corr)
    if (blockIdx.x == 0) {
        if (t < 3) g_ecnt[t][b] = 0;
        if (t == 3) g_done[b] = 0;
        if (t == 4) g_scnt_b[b] = 0;
    }

    // phase 0: cp.async 256 w-rows x 128B segments into smem
    const float* src = ret + (size_t)b * WIN * NA + n0;
    const uint32_t sbase = smem_u32(fsm);
#pragma unroll
    for (int it = 0; it < 4; it++) {
        int idx = t + it * 512;
        int w = idx >> 3, sg = idx & 7;
        CP16(sbase + w * 128 + sg * 16, src + (size_t)w * NA + sg * 4);
    }
    CPCOMMIT();
    CPWAIT0();
    __syncthreads();

    // phase 1: read 16 column values once into registers; partial sums
    const int a = t & 31, q = t >> 5;
    float x[16];
    {
        float s = 0.f, s2 = 0.f;
#pragma unroll
        for (int i = 0; i < 16; i++) {
            x[i] = fsm[q * 16 + i][a];
            s += x[i]; s2 += x[i] * x[i];
        }
        ps[q][a] = s; ps2[q][a] = s2;
    }
    __syncthreads();

    // phase 2: combine partials (fixed ascending order), stats
    if (q == 0) {
        float ss = 0.f, ss2 = 0.f;
#pragma unroll
        for (int k = 0; k < 16; k++) { ss += ps[k][a]; ss2 += ps2[k][a]; }
        float mean = ss * (1.0f / WIN);
        float var = fmaxf((ss2 - ss * mean) * (1.0f / (WIN - 1)), 0.0f);
        mean_s[a] = mean;
        inv_s[a] = 1.0f / (sqrtf(var) + 1e-8f);
    }
    __syncthreads();

    // phase 3: convert the same registers, store 32B per thread
    {
        const float mean = mean_s[a], inv = inv_s[a];
        unsigned int hw[8];
#pragma unroll
        for (int k = 0; k < 8; k++) {
            float x0 = (x[2 * k] - mean) * inv;
            float x1 = (x[2 * k + 1] - mean) * inv;
            __nv_bfloat16 h0 = __float2bfloat16(x0);
            __nv_bfloat16 h1 = __float2bfloat16(x1);
            hw[k] = ((unsigned int)__bfloat16_as_ushort(h1) << 16)
                  | __bfloat16_as_ushort(h0);
        }
        __nv_bfloat16* dh = &g_h[b][n0 + a][q * 16];
        *(uint4*)(dh + 0) = make_uint4(hw[0], hw[1], hw[2], hw[3]);
        *(uint4*)(dh + 8) = make_uint4(hw[4], hw[5], hw[6], hw[7]);
    }
}

// ---- corr GEMM (h.h, mma.sync bf16, K=256, 3-stage cp.async) + fused betti ---
// CTA tile 128x64, 8 warps (4x2). Grid: 20 upper-tri tiles x 32 b.
// Last-finishing CTA per batch runs suspect fixup + components for all 3 tt.
__global__ void __launch_bounds__(256, 3)
corr_mma_kernel(const float* __restrict__ ret, float* __restrict__ out) {
    extern __shared__ __align__(128) unsigned char dsm[];
    const uint32_t sb = smem_u32(dsm);

    const int TI[NTILE] = {0,0,0,0,0,0,0,0, 1,1,1,1,1,1, 2,2,2,2, 3,3};
    const int TJ[NTILE] = {0,1,2,3,4,5,6,7, 2,3,4,5,6,7, 4,5,6,7, 6,7};
    const int b  = blockIdx.y;
    const int i0 = TI[blockIdx.x] * 128;
    const int j0 = TJ[blockIdx.x] * 64;
    const int t = threadIdx.x;
    const int wid = t >> 5, lane = t & 31;
    const int mw = wid >> 1;
    const int nw = wid & 1;

    float acc[2][4][4];
#pragma unroll
    for (int mt = 0; mt < 2; mt++)
#pragma unroll
        for (int nt = 0; nt < 4; nt++)
#pragma unroll
            for (int q = 0; q < 4; q++) acc[mt][nt][q] = 0.f;

    const int arow = t >> 1, ahalf = t & 1;
    const uint32_t aswz = SW128(arow * 128 + ahalf * 64);
    const int brow = t >> 2, bq = t & 3;
    const uint32_t bswz = SW128(brow * 128 + bq * 32);

    const __nv_bfloat16* rowA = &g_h[b][i0 + arow][0];
    const __nv_bfloat16* rowB = &g_h[b][j0 + brow][0];

    auto load_chunk = [&](int c) {
        const uint32_t base = sb + (c % NSTG) * STAGE_BYTES;
        const __nv_bfloat16* sA = rowA + c * KCH + ahalf * 32;
#pragma unroll
        for (int f = 0; f < 4; f++)
            CP16(base + (aswz ^ (f * 16)), sA + f * 8);
        const __nv_bfloat16* sB = rowB + c * KCH + bq * 16;
        CP16(base + 16384 + bswz, sB);
        CP16(base + 16384 + (bswz ^ 16), sB + 8);
        CPCOMMIT();
    };

    load_chunk(0);
    load_chunk(1);

    for (int c = 0; c < NCH; c++) {
        if (c < NCH - 1) CPWAIT1(); else CPWAIT0();
        __syncthreads();

        const uint32_t sbA = sb + (c % NSTG) * STAGE_BYTES;
        const uint32_t sbB = sbA + 16384;
#pragma unroll
        for (int ks = 0; ks < 4; ks++) {
            const int kb = ks * 32;
            uint32_t af[2][4];
#pragma unroll
            for (int mt = 0; mt < 2; mt++) {
                int row = mw * 32 + mt * 16 + ((lane >> 3) & 1) * 8 + (lane & 7);
                int kbyte = kb + (lane >> 4) * 16;
                uint32_t addr = sbA + SW128(row * 128 + kbyte);
                asm volatile("ldmatrix.sync.aligned.m8n8.x4.shared.b16 {%0,%1,%2,%3}, [%4];"
                    : "=r"(af[mt][0]), "=r"(af[mt][1]), "=r"(af[mt][2]), "=r"(af[mt][3])
                    : "r"(addr));
            }
            uint32_t bf[4][2];
#pragma unroll
            for (int np = 0; np < 2; np++) {
                int row = nw * 32 + np * 16 + ((lane >> 4) & 1) * 8 + (lane & 7);
                int kbyte = kb + ((lane >> 3) & 1) * 16;
                uint32_t addr = sbB + SW128(row * 128 + kbyte);
                asm volatile("ldmatrix.sync.aligned.m8n8.x4.shared.b16 {%0,%1,%2,%3}, [%4];"
                    : "=r"(bf[2*np][0]), "=r"(bf[2*np][1]),
                      "=r"(bf[2*np+1][0]), "=r"(bf[2*np+1][1])
                    : "r"(addr));
            }
#pragma unroll
            for (int mt = 0; mt < 2; mt++)
#pragma unroll
                for (int nt = 0; nt < 4; nt++)
                    asm volatile(
                        "mma.sync.aligned.m16n8k16.row.col.f32.bf16.bf16.f32 "
                        "{%0,%1,%2,%3}, {%4,%5,%6,%7}, {%8,%9}, {%0,%1,%2,%3};"
                        : "+f"(acc[mt][nt][0]), "+f"(acc[mt][nt][1]),
                          "+f"(acc[mt][nt][2]), "+f"(acc[mt][nt][3])
                        : "r"(af[mt][0]), "r"(af[mt][1]), "r"(af[mt][2]), "r"(af[mt][3]),
                          "r"(bf[nt][0]), "r"(bf[nt][1]));
        }

        if (c + 2 < NCH) load_chunk(c + 2);
        else CPCOMMIT();   // keep group accounting uniform
    }

    // epilogue: banded threshold -> edges / per-batch suspects
    const float TH[3] = {0.3f, 0.5f, 0.7f};
#pragma unroll
    for (int mt = 0; mt < 2; mt++) {
#pragma unroll
        for (int nt = 0; nt < 4; nt++) {
            int gi0 = i0 + mw * 32 + mt * 16 + (lane >> 2);
            int gj0 = j0 + nw * 32 + nt * 8 + 2 * (lane & 3);
#pragma unroll
            for (int q = 0; q < 4; q++) {
                int gi = gi0 + (q >> 1) * 8;
                int gj = gj0 + (q & 1);
                float v = fabsf(acc[mt][nt][q] * (1.0f / 256.0f));
                if (gi < gj && v > TH[0] - BAND) {
                    unsigned int e = ((unsigned int)gi << 16) | (unsigned int)gj;
                    unsigned int mask = 0;
#pragma unroll
                    for (int k = 0; k < 3; k++) {
                        if (v > TH[k] + BAND) {
                            int p = atomicAdd(&g_ecnt[k][b], 1);
                            g_edges[k][b][p] = e;
                        } else if (v > TH[k] - BAND) {
                            mask |= 1u << k;
                        }
                    }
                    if (mask) {
                        int p = atomicAdd(&g_scnt_b[b], 1);
                        if (p < SCAPB)
                            g_susp[b][p] = (mask << 23)
                                         | ((unsigned int)gi << 9) | (unsigned int)gj;
                    }
                }
            }
        }
    }

    // ---- last-CTA-per-batch: fused betti (fp64 fixup + components, 3 tt) ----
    __shared__ int done_rank;
    __shared__ int changed, comp_cnt;
    __threadfence();
    __syncthreads();
    if (t == 0) done_rank = atomicAdd(&g_done[b], 1);
    __syncthreads();
    if (done_rank != NTILE - 1) return;
    __threadfence();   // acquire side: all batch-b writes now visible

    // smem reuse (GEMM stages are dead now)
    int* label          = (int*)dsm;                       // 512 ints
    unsigned int* extra = (unsigned int*)(dsm + 2048);     // 3 x 256
    int* exc            = (int*)(dsm + 2048 + 3 * 256 * 4);
    double* wsum        = (double*)(dsm + 8192);           // 8 warps x 5

    if (t < 3) exc[t] = 0;
    __syncthreads();

    // fp64 exact corr for in-band suspects of this batch
    const int scnt = min(g_scnt_b[b], SCAPB);
    const double THD[3] = {0.3, 0.5, 0.7};
    for (int s = 0; s < scnt; s++) {
        unsigned int wd = g_susp[b][s];
        int gj = wd & 511, gi = (wd >> 9) & 511;
        int mask = (wd >> 23) & 7;

        double xi = (double)ret[((size_t)b * WIN + t) * NA + gi];
        double xj = (double)ret[((size_t)b * WIN + t) * NA + gj];
        double p0 = xi, p1 = xi * xi, p2 = xj, p3 = xj * xj, p4 = xi * xj;
#pragma unroll
        for (int o = 16; o; o >>= 1) {
            p0 += __shfl_down_sync(0xFFFFFFFFu, p0, o);
            p1 += __shfl_down_sync(0xFFFFFFFFu, p1, o);
            p2 += __shfl_down_sync(0xFFFFFFFFu, p2, o);
            p3 += __shfl_down_sync(0xFFFFFFFFu, p3, o);
            p4 += __shfl_down_sync(0xFFFFFFFFu, p4, o);
        }
        if (lane == 0) {
            wsum[wid * 5 + 0] = p0; wsum[wid * 5 + 1] = p1;
            wsum[wid * 5 + 2] = p2; wsum[wid * 5 + 3] = p3;
            wsum[wid * 5 + 4] = p4;
        }
        __syncthreads();
        if (t == 0) {
            double r0 = 0, r1 = 0, r2 = 0, r3 = 0, r4 = 0;
#pragma unroll
            for (int k = 0; k < 8; k++) {
                r0 += wsum[k * 5 + 0]; r1 += wsum[k * 5 + 1];
                r2 += wsum[k * 5 + 2]; r3 += wsum[k * 5 + 3];
                r4 += wsum[k * 5 + 4];
            }
            double mi = r0 / 256.0, mj = r2 / 256.0;
            double vi = (r1 - r0 * mi) / 255.0;
            double vj = (r3 - r2 * mj) / 255.0;
            double di = sqrt(vi > 0 ? vi : 0) + 1e-8;
            double dj = sqrt(vj > 0 ? vj : 0) + 1e-8;
            double cov = r4 - 256.0 * mi * mj;
            double v = fabs(cov / (di * dj) / 256.0);
            unsigned int e = ((unsigned int)gi << 16) | (unsigned int)gj;
            for (int k = 0; k < 3; k++)
                if (((mask >> k) & 1) && v > THD[k] && exc[k] < 256)
                    extra[k * 256 + exc[k]++] = e;
        }
        __syncthreads();
    }

    // components + betti for each threshold (256 threads over 512 nodes)
    for (int tt = 0; tt < 3; tt++) {
        const int cnt = g_ecnt[tt][b];
        const int ecx = exc[tt];
        const unsigned int* el = &g_edges[tt][b][0];

        for (int n = t; n < NA; n += 256) label[n] = n;
        if (t == 0) comp_cnt = 0;
        __syncthreads();

        while (true) {
            if (t == 0) changed = 0;
            __syncthreads();
            for (int e = t; e < cnt; e += 256) {
                unsigned int pk = el[e];
                int i = pk >> 16, j = pk & 0xFFFF;
                int li = label[i], lj = label[j];
                if (li < lj) { atomicMin(&label[j], li); changed = 1; }
                else if (lj < li) { atomicMin(&label[i], lj); changed = 1; }
            }
            for (int e = t; e < ecx; e += 256) {
                unsigned int pk = extra[tt * 256 + e];
                int i = pk >> 16, j = pk & 0xFFFF;
                int li = label[i], lj = label[j];
                if (li < lj) { atomicMin(&label[j], li); changed = 1; }
                else if (lj < li) { atomicMin(&label[i], lj); changed = 1; }
            }
            __syncthreads();
            for (int n = t; n < NA; n += 256) {
                int l = label[n];
                int ll = label[l];
                if (ll < l) { label[n] = ll; changed = 1; }
            }
            __syncthreads();
            if (!changed) break;
            __syncthreads();
        }

        int isrep = 0;
        for (int n = t; n < NA; n += 256) isrep += (label[n] == n) ? 1 : 0;
#pragma unroll
        for (int o = 16; o; o >>= 1) isrep += __shfl_down_sync(0xFFFFFFFFu, isrep, o);
        if (lane == 0) atomicAdd(&comp_cnt, isrep);
        __syncthreads();

        if (t == 0) {
            float comp = (float)comp_cnt;
            float edges = (float)(cnt + ecx);
            float b1 = fmaxf(0.0f, edges - (float)NA + comp);
            out[b * 6 + tt * 2 + 0] = comp * (1.0f / NA);
            out[b * 6 + tt * 2 + 1] = b1 * (1.0f / NA);
        }
        __syncthreads();
    }
}

// ---------------- launch ----------------
extern "C" void kernel_launch(void* const* d_in, const int* in_sizes, int n_in,
                              void* d_out, int out_size) {
    const float* ret = (const float*)d_in[0];
    float* out = (float*)d_out;
    (void)in_sizes; (void)n_in; (void)out_size;

    cudaFuncSetAttribute(corr_mma_kernel,
                         cudaFuncAttributeMaxDynamicSharedMemorySize, SMEM_DYN);

    { dim3 g(NA / 32, BATCH); convert_kernel<<<g, 512>>>(ret); }
    { dim3 g(NTILE, BATCH);   corr_mma_kernel<<<g, 256, SMEM_DYN>>>(ret, out); }
}